// round 8
// baseline (speedup 1.0000x reference)
#include <cuda_runtime.h>
#include <cuda_fp16.h>
#include <cstdint>

// ---------------------------------------------------------------------------
// Attention_37074157699274 — round 8: GEMM re-tiled for issue parallelism.
// 512 threads, CTA 256x128, 16 warps (4Mx4N), warp tile 64x32 -> 64-reg acc,
// 4 warps/SMSP (was 2). 4-stage cp.async + ldmatrix unchanged.
//   K0: x -> fp16 ; T1/T2: weights -> [N,K] fp16
//   K1: qkv = xh @ W_qkv ; K2: attn ; K3: out = attn @ W_out + b
// ---------------------------------------------------------------------------

#define TOKENS   131072
#define GROUPS   4096
#define DIMX     256
#define NQKV     1536
#define INNER    512
#define HEADS    8
#define DH       64
#define ATT_SCALE 0.125f

__device__ __half g_xh  [(size_t)TOKENS * DIMX];
__device__ __half g_qkv [(size_t)TOKENS * NQKV];
__device__ __half g_attn[(size_t)TOKENS * INNER];
__device__ __half g_WqkvT[(size_t)NQKV * DIMX];
__device__ __half g_WoutT[(size_t)DIMX * INNER];

// ------------------------- helpers ------------------------------------------

__device__ __forceinline__ uint32_t pack2h(float x, float y) {
    __half2 h = __halves2half2(__float2half_rn(x), __float2half_rn(y));
    return *reinterpret_cast<uint32_t*>(&h);
}
__device__ __forceinline__ uint32_t smem_u32(const void* p) {
    uint32_t a;
    asm("{ .reg .u64 t; cvta.to.shared.u64 t, %1; cvt.u32.u64 %0, t; }"
        : "=r"(a) : "l"(p));
    return a;
}
__device__ __forceinline__ void cp16(uint32_t saddr, const void* gptr) {
    asm volatile("cp.async.cg.shared.global [%0], [%1], 16;"
                 :: "r"(saddr), "l"(gptr) : "memory");
}
__device__ __forceinline__ void ldsm4(uint32_t r[4], uint32_t addr) {
    asm volatile("ldmatrix.sync.aligned.m8n8.x4.shared.b16 {%0,%1,%2,%3}, [%4];"
                 : "=r"(r[0]), "=r"(r[1]), "=r"(r[2]), "=r"(r[3]) : "r"(addr));
}
__device__ __forceinline__ void ldsm4t(uint32_t r[4], uint32_t addr) {
    asm volatile("ldmatrix.sync.aligned.m8n8.x4.trans.shared.b16 {%0,%1,%2,%3}, [%4];"
                 : "=r"(r[0]), "=r"(r[1]), "=r"(r[2]), "=r"(r[3]) : "r"(addr));
}
__device__ __forceinline__ void mma_f16(float c[4], uint32_t a0, uint32_t a1,
                                        uint32_t a2, uint32_t a3,
                                        uint32_t b0, uint32_t b1) {
    asm volatile(
        "mma.sync.aligned.m16n8k16.row.col.f32.f16.f16.f32 "
        "{%0,%1,%2,%3}, {%4,%5,%6,%7}, {%8,%9}, {%0,%1,%2,%3};\n"
        : "+f"(c[0]), "+f"(c[1]), "+f"(c[2]), "+f"(c[3])
        : "r"(a0), "r"(a1), "r"(a2), "r"(a3), "r"(b0), "r"(b1));
}

// ------------------------- GEMM ---------------------------------------------
// C[M,N] = A[M,K] @ Bt[N,K]^T (+bias). CTA 256x128, K-chunk 32, 4-stage
// cp.async, 512 threads = 16 warps 4(M)x4(N), warp tile 64x32, ldmatrix.
// smem rows = 40 halfs (80 B).

#define STRB   80
#define A_BYTES (256 * STRB)              // 20480
#define B_BYTES (128 * STRB)              // 10240
#define STG_BYTES (A_BYTES + B_BYTES)     // 30720
#define NSTG   4
#define GSM_BYTES (NSTG * STG_BYTES)      // 122880

template<typename TC>
__global__ __launch_bounds__(512, 1)
void gemm_h(const __half* __restrict__ A, const __half* __restrict__ Bt,
            TC* __restrict__ C, int K, int N, const float* __restrict__ bias)
{
    extern __shared__ __half sh[];
    const uint32_t sb = smem_u32(sh);

    const int t     = threadIdx.x;
    const int lane  = t & 31;
    const int warp  = t >> 5;             // 0..15
    const int warpM = warp & 3;           // 0..3 -> rows [warpM*64, +64)
    const int warpN = warp >> 2;          // 0..3 -> cols [warpN*32, +32)

    const size_t rowBase = (size_t)blockIdx.y * 256;
    const int    colBase = blockIdx.x * 128;
    const int NC = K >> 5;

    float acc[4][4][4];
    #pragma unroll
    for (int mt = 0; mt < 4; mt++)
        #pragma unroll
        for (int nt = 0; nt < 4; nt++)
            #pragma unroll
            for (int i = 0; i < 4; i++) acc[mt][nt][i] = 0.f;

    const __half* Ab = A  + rowBase * K;
    const __half* Bb = Bt + (size_t)colBase * K;

    auto stage = [&](int kc) {
        const uint32_t aD = sb + (kc & (NSTG - 1)) * STG_BYTES;
        const uint32_t bD = aD + A_BYTES;
        const __half* As = Ab + kc * 32;
        const __half* Bs = Bb + kc * 32;
        #pragma unroll
        for (int i = 0; i < 2; i++) {            // A: 1024 16B-granules
            int g = i * 512 + t, r = g >> 2, s = g & 3;
            cp16(aD + r * STRB + s * 16, As + (size_t)r * K + s * 8);
        }
        {                                         // B: 512 granules
            int r = t >> 2, s = t & 3;
            cp16(bD + r * STRB + s * 16, Bs + (size_t)r * K + s * 8);
        }
        asm volatile("cp.async.commit_group;" ::: "memory");
    };

    stage(0); stage(1); stage(2);

    const int lr    = lane & 15;
    const int aKoff = (lane & 16) ? 16 : 0;
    const int bRow  = (lane & 7) + ((lane & 16) ? 8 : 0);
    const int bKoff = (lane & 8) ? 16 : 0;

    for (int kc = 0; kc < NC; kc++) {
        if (kc < NC - 2)       asm volatile("cp.async.wait_group 2;" ::: "memory");
        else if (kc == NC - 2) asm volatile("cp.async.wait_group 1;" ::: "memory");
        else                   asm volatile("cp.async.wait_group 0;" ::: "memory");
        __syncthreads();
        if (kc + 3 < NC) stage(kc + 3);

        const uint32_t aB = sb + (kc & (NSTG - 1)) * STG_BYTES;
        const uint32_t bB = aB + A_BYTES;

        #pragma unroll
        for (int ks = 0; ks < 2; ks++) {
            const int k0b = ks * 32;
            uint32_t a[4][4], b[2][4];
            #pragma unroll
            for (int mt = 0; mt < 4; mt++)
                ldsm4(a[mt], aB + (warpM * 64 + mt * 16 + lr) * STRB + k0b + aKoff);
            #pragma unroll
            for (int np = 0; np < 2; np++)
                ldsm4(b[np], bB + (warpN * 32 + np * 16 + bRow) * STRB + k0b + bKoff);
            #pragma unroll
            for (int nt = 0; nt < 4; nt++) {
                uint32_t b0 = b[nt >> 1][(nt & 1) * 2];
                uint32_t b1 = b[nt >> 1][(nt & 1) * 2 + 1];
                #pragma unroll
                for (int mt = 0; mt < 4; mt++)
                    mma_f16(acc[mt][nt], a[mt][0], a[mt][1], a[mt][2], a[mt][3],
                            b0, b1);
            }
        }
    }

    // ---- epilogue
    #pragma unroll
    for (int mt = 0; mt < 4; mt++) {
        size_t row = rowBase + warpM * 64 + mt * 16 + (lane >> 2);
        #pragma unroll
        for (int nt = 0; nt < 4; nt++) {
            int col = colBase + warpN * 32 + nt * 8 + 2 * (lane & 3);
            if constexpr (sizeof(TC) == 2) {
                __half* cp = (__half*)C;
                *(uint32_t*)(cp + row * N + col) =
                    pack2h(acc[mt][nt][0], acc[mt][nt][1]);
                *(uint32_t*)(cp + (row + 8) * N + col) =
                    pack2h(acc[mt][nt][2], acc[mt][nt][3]);
            } else {
                float b0 = 0.f, b1 = 0.f;
                if (bias) { b0 = bias[col]; b1 = bias[col + 1]; }
                float* cp = (float*)C;
                *(float2*)(cp + row * N + col) =
                    make_float2(acc[mt][nt][0] + b0, acc[mt][nt][1] + b1);
                *(float2*)(cp + (row + 8) * N + col) =
                    make_float2(acc[mt][nt][2] + b0, acc[mt][nt][3] + b1);
            }
        }
    }
}

// ------------------------- aux kernels --------------------------------------

__global__ void f2h_kernel(const float* __restrict__ in, __half* __restrict__ out,
                           int n4)
{
    int i = blockIdx.x * blockDim.x + threadIdx.x;
    if (i < n4) {
        float4 v = ((const float4*)in)[i];
        ((uint2*)out)[i] = make_uint2(pack2h(v.x, v.y), pack2h(v.z, v.w));
    }
}

__global__ void transpose_h(const float* __restrict__ in, __half* __restrict__ out,
                            int R, int C)
{
    __shared__ float tile[32][33];
    int c0 = blockIdx.x * 32, r0 = blockIdx.y * 32;
    #pragma unroll
    for (int i = threadIdx.y; i < 32; i += 8)
        tile[i][threadIdx.x] = in[(size_t)(r0 + i) * C + c0 + threadIdx.x];
    __syncthreads();
    #pragma unroll
    for (int i = threadIdx.y; i < 32; i += 8)
        out[(size_t)(c0 + i) * R + r0 + threadIdx.x] =
            __float2half_rn(tile[threadIdx.x][i]);
}

// ------------------------- K2: attention core (unchanged from r7) -----------

#define QS 72

__global__ __launch_bounds__(128)
void attn_core(const __half* __restrict__ qkv, __half* __restrict__ o)
{
    __shared__ __half Qs[32 * QS];
    __shared__ __half Ks[32 * QS];
    __shared__ __half Vs[32 * QS];
    __shared__ float  S [32][36];

    const int t    = threadIdx.x;
    const int lane = t & 31;
    const int warp = t >> 5;
    const int g    = blockIdx.x;
    const int h    = g & 7;
    const size_t tokBase = (size_t)(g >> 3) * 32;

    const __half* base = qkv + tokBase * NQKV + h * DH;

    #pragma unroll
    for (int i = 0; i < 4; i++) {
        int idx = i * 128 + t;
        int r   = idx >> 4;
        int sg  = idx & 15;
        const __half* rp = base + (size_t)r * NQKV + sg * 4;
        *(uint2*)(Qs + r * QS + sg * 4) = *(const uint2*)(rp);
        *(uint2*)(Ks + r * QS + sg * 4) = *(const uint2*)(rp + 512);
        *(uint2*)(Vs + r * QS + sg * 4) = *(const uint2*)(rp + 1024);
    }
    __syncthreads();

    const uint32_t qb = smem_u32(Qs);
    const uint32_t kb = smem_u32(Ks);
    const uint32_t vb = smem_u32(Vs);
    const int lr    = lane & 15;
    const int aKoff = (lane & 16) ? 16 : 0;
    const int bRow  = (lane & 7) + ((lane & 16) ? 8 : 0);
    const int bKoff = (lane & 8) ? 16 : 0;
    const int vCoff = (lane & 16) ? 16 : 0;

    // ---- S = Q K^T
    const int mt  = warp & 1;
    const int ntb = (warp >> 1) * 2;
    float sacc[2][4] = {{0.f,0.f,0.f,0.f},{0.f,0.f,0.f,0.f}};
    #pragma unroll
    for (int ks = 0; ks < 4; ks++) {
        const int k0b = ks * 32;
        uint32_t a[4], b[4];
        ldsm4(a, qb + (mt * 16 + lr) * (QS * 2) + k0b + aKoff);
        ldsm4(b, kb + (ntb * 8 + bRow) * (QS * 2) + k0b + bKoff);
        mma_f16(sacc[0], a[0], a[1], a[2], a[3], b[0], b[1]);
        mma_f16(sacc[1], a[0], a[1], a[2], a[3], b[2], b[3]);
    }
    #pragma unroll
    for (int n = 0; n < 2; n++) {
        int row = mt * 16 + (lane >> 2);
        int col = (ntb + n) * 8 + 2 * (lane & 3);
        S[row    ][col    ] = sacc[n][0] * ATT_SCALE;
        S[row    ][col + 1] = sacc[n][1] * ATT_SCALE;
        S[row + 8][col    ] = sacc[n][2] * ATT_SCALE;
        S[row + 8][col + 1] = sacc[n][3] * ATT_SCALE;
    }
    __syncthreads();

    // ---- softmax
    #pragma unroll
    for (int rr = 0; rr < 8; rr++) {
        int row = warp * 8 + rr;
        float v = S[row][lane];
        float m = v;
        #pragma unroll
        for (int off = 16; off; off >>= 1) m = fmaxf(m, __shfl_xor_sync(~0u, m, off));
        float e = __expf(v - m);
        float s = e;
        #pragma unroll
        for (int off = 16; off; off >>= 1) s += __shfl_xor_sync(~0u, s, off);
        S[row][lane] = e / s;
    }
    __syncthreads();

    // ---- O = P V
    const int dBase = (warp >> 1) * 32;
    float oacc[4][4];
    #pragma unroll
    for (int n = 0; n < 4; n++)
        #pragma unroll
        for (int i = 0; i < 4; i++) oacc[n][i] = 0.f;

    #pragma unroll
    for (int ks = 0; ks < 2; ks++) {
        const int j0 = ks * 16;
        int r0 = mt * 16 + (lane >> 2);
        int c  = j0 + (lane & 3) * 2;
        uint32_t a0 = pack2h(S[r0    ][c    ], S[r0    ][c + 1]);
        uint32_t a1 = pack2h(S[r0 + 8][c    ], S[r0 + 8][c + 1]);
        uint32_t a2 = pack2h(S[r0    ][c + 8], S[r0    ][c + 9]);
        uint32_t a3 = pack2h(S[r0 + 8][c + 8], S[r0 + 8][c + 9]);
        #pragma unroll
        for (int hf = 0; hf < 2; hf++) {
            uint32_t b[4];
            int dA = dBase + hf * 16;
            ldsm4t(b, vb + (j0 + lr) * (QS * 2) + dA * 2 + vCoff);
            mma_f16(oacc[hf * 2    ], a0, a1, a2, a3, b[0], b[1]);
            mma_f16(oacc[hf * 2 + 1], a0, a1, a2, a3, b[2], b[3]);
        }
    }

    __half* obase = o + tokBase * INNER + h * DH;
    const int nt4 = (warp >> 1) * 4;
    #pragma unroll
    for (int n = 0; n < 4; n++) {
        int row = mt * 16 + (lane >> 2);
        int col = (nt4 + n) * 8 + 2 * (lane & 3);
        *(uint32_t*)(obase + (size_t)row * INNER + col) =
            pack2h(oacc[n][0], oacc[n][1]);
        *(uint32_t*)(obase + (size_t)(row + 8) * INNER + col) =
            pack2h(oacc[n][2], oacc[n][3]);
    }
}

// ------------------------- launch -------------------------------------------

extern "C" void kernel_launch(void* const* d_in, const int* in_sizes, int n_in,
                              void* d_out, int out_size)
{
    const float* x     = (const float*)d_in[0];
    const float* W_qkv = (const float*)d_in[1];
    const float* W_out = (const float*)d_in[2];
    const float* b_out = (const float*)d_in[3];
    float* out = (float*)d_out;

    __half *xh, *qkv, *att, *wqT, *woT;
    cudaGetSymbolAddress((void**)&xh,  g_xh);
    cudaGetSymbolAddress((void**)&qkv, g_qkv);
    cudaGetSymbolAddress((void**)&att, g_attn);
    cudaGetSymbolAddress((void**)&wqT, g_WqkvT);
    cudaGetSymbolAddress((void**)&woT, g_WoutT);

    cudaFuncSetAttribute(gemm_h<__half>,
                         cudaFuncAttributeMaxDynamicSharedMemorySize, GSM_BYTES);
    cudaFuncSetAttribute(gemm_h<float>,
                         cudaFuncAttributeMaxDynamicSharedMemorySize, GSM_BYTES);

    const int n4 = TOKENS * DIMX / 4;
    f2h_kernel<<<n4 / 256, 256>>>(x, xh, n4);

    transpose_h<<<dim3(NQKV / 32, DIMX / 32), dim3(32, 8)>>>(W_qkv, wqT, DIMX, NQKV);
    transpose_h<<<dim3(DIMX / 32, INNER / 32), dim3(32, 8)>>>(W_out, woT, INNER, DIMX);

    // K1: qkv = xh @ W_qkv  (M=131072, K=256, N=1536)  grid (12, 512)
    gemm_h<__half><<<dim3(NQKV / 128, TOKENS / 256), 512, GSM_BYTES>>>(
        xh, wqT, qkv, DIMX, NQKV, nullptr);

    // K2: attention
    attn_core<<<GROUPS * HEADS, 128>>>(qkv, att);

    // K3: out = att @ W_out + b  (M=131072, K=512, N=256)  grid (2, 512)
    gemm_h<float><<<dim3(DIMX / 128, TOKENS / 256), 512, GSM_BYTES>>>(
        att, woT, out, INNER, DIMX, b_out);
}

// round 9
// speedup vs baseline: 1.1265x; 1.1265x over previous
#include <cuda_runtime.h>
#include <cuda_fp16.h>
#include <cstdint>

// ---------------------------------------------------------------------------
// Attention_37074157699274 — round 9: GEMM sized for 2 resident CTAs/SM.
// CTA 128x128, 256 thr, 8 warps (2Mx4N), warp tile 64x32 (64-reg acc),
// 4-stage cp.async @20KB -> 80KB smem/CTA; launch_bounds(256,2) caps regs.
// Two co-resident CTAs hide each other's barrier/pipeline stalls.
//   K0: x->fp16 ; T1/T2: weights -> [N,K] fp16
//   K1: qkv = xh @ W_qkv ; K2: attn ; K3: out = attn @ W_out + b
// ---------------------------------------------------------------------------

#define TOKENS   131072
#define GROUPS   4096
#define DIMX     256
#define NQKV     1536
#define INNER    512
#define HEADS    8
#define DH       64
#define ATT_SCALE 0.125f

__device__ __half g_xh  [(size_t)TOKENS * DIMX];
__device__ __half g_qkv [(size_t)TOKENS * NQKV];
__device__ __half g_attn[(size_t)TOKENS * INNER];
__device__ __half g_WqkvT[(size_t)NQKV * DIMX];
__device__ __half g_WoutT[(size_t)DIMX * INNER];

// ------------------------- helpers ------------------------------------------

__device__ __forceinline__ uint32_t pack2h(float x, float y) {
    __half2 h = __halves2half2(__float2half_rn(x), __float2half_rn(y));
    return *reinterpret_cast<uint32_t*>(&h);
}
__device__ __forceinline__ uint32_t smem_u32(const void* p) {
    uint32_t a;
    asm("{ .reg .u64 t; cvta.to.shared.u64 t, %1; cvt.u32.u64 %0, t; }"
        : "=r"(a) : "l"(p));
    return a;
}
__device__ __forceinline__ void cp16(uint32_t saddr, const void* gptr) {
    asm volatile("cp.async.cg.shared.global [%0], [%1], 16;"
                 :: "r"(saddr), "l"(gptr) : "memory");
}
__device__ __forceinline__ void ldsm4(uint32_t r[4], uint32_t addr) {
    asm volatile("ldmatrix.sync.aligned.m8n8.x4.shared.b16 {%0,%1,%2,%3}, [%4];"
                 : "=r"(r[0]), "=r"(r[1]), "=r"(r[2]), "=r"(r[3]) : "r"(addr));
}
__device__ __forceinline__ void ldsm4t(uint32_t r[4], uint32_t addr) {
    asm volatile("ldmatrix.sync.aligned.m8n8.x4.trans.shared.b16 {%0,%1,%2,%3}, [%4];"
                 : "=r"(r[0]), "=r"(r[1]), "=r"(r[2]), "=r"(r[3]) : "r"(addr));
}
__device__ __forceinline__ void mma_f16(float c[4], uint32_t a0, uint32_t a1,
                                        uint32_t a2, uint32_t a3,
                                        uint32_t b0, uint32_t b1) {
    asm volatile(
        "mma.sync.aligned.m16n8k16.row.col.f32.f16.f16.f32 "
        "{%0,%1,%2,%3}, {%4,%5,%6,%7}, {%8,%9}, {%0,%1,%2,%3};\n"
        : "+f"(c[0]), "+f"(c[1]), "+f"(c[2]), "+f"(c[3])
        : "r"(a0), "r"(a1), "r"(a2), "r"(a3), "r"(b0), "r"(b1));
}

// ------------------------- GEMM ---------------------------------------------
// C[M,N] = A[M,K] @ Bt[N,K]^T (+bias). CTA 128x128, K-chunk 32, 4-stage
// cp.async, 256 threads = 8 warps 2(M)x4(N), warp tile 64x32, ldmatrix.
// smem rows = 40 halfs (80 B).

#define STRB   80
#define A_BYTES (128 * STRB)              // 10240
#define B_BYTES (128 * STRB)              // 10240
#define STG_BYTES (A_BYTES + B_BYTES)     // 20480
#define NSTG   4
#define GSM_BYTES (NSTG * STG_BYTES)      // 81920

template<typename TC>
__global__ __launch_bounds__(256, 2)
void gemm_h(const __half* __restrict__ A, const __half* __restrict__ Bt,
            TC* __restrict__ C, int K, int N, const float* __restrict__ bias)
{
    extern __shared__ __half sh[];
    const uint32_t sb = smem_u32(sh);

    const int t     = threadIdx.x;
    const int lane  = t & 31;
    const int warp  = t >> 5;             // 0..7
    const int warpM = warp & 1;           // 0..1 -> rows [warpM*64, +64)
    const int warpN = warp >> 1;          // 0..3 -> cols [warpN*32, +32)

    const size_t rowBase = (size_t)blockIdx.y * 128;
    const int    colBase = blockIdx.x * 128;
    const int NC = K >> 5;

    float acc[4][4][4];
    #pragma unroll
    for (int mt = 0; mt < 4; mt++)
        #pragma unroll
        for (int nt = 0; nt < 4; nt++)
            #pragma unroll
            for (int i = 0; i < 4; i++) acc[mt][nt][i] = 0.f;

    const __half* Ab = A  + rowBase * K;
    const __half* Bb = Bt + (size_t)colBase * K;

    auto stage = [&](int kc) {
        const uint32_t aD = sb + (kc & (NSTG - 1)) * STG_BYTES;
        const uint32_t bD = aD + A_BYTES;
        const __half* As = Ab + kc * 32;
        const __half* Bs = Bb + kc * 32;
        #pragma unroll
        for (int i = 0; i < 2; i++) {            // A: 512 16B-granules
            int g = i * 256 + t, r = g >> 2, s = g & 3;
            cp16(aD + r * STRB + s * 16, As + (size_t)r * K + s * 8);
        }
        #pragma unroll
        for (int i = 0; i < 2; i++) {            // B: 512 granules
            int g = i * 256 + t, r = g >> 2, s = g & 3;
            cp16(bD + r * STRB + s * 16, Bs + (size_t)r * K + s * 8);
        }
        asm volatile("cp.async.commit_group;" ::: "memory");
    };

    stage(0); stage(1); stage(2);

    const int lr    = lane & 15;
    const int aKoff = (lane & 16) ? 16 : 0;
    const int bRow  = (lane & 7) + ((lane & 16) ? 8 : 0);
    const int bKoff = (lane & 8) ? 16 : 0;

    for (int kc = 0; kc < NC; kc++) {
        if (kc < NC - 2)       asm volatile("cp.async.wait_group 2;" ::: "memory");
        else if (kc == NC - 2) asm volatile("cp.async.wait_group 1;" ::: "memory");
        else                   asm volatile("cp.async.wait_group 0;" ::: "memory");
        __syncthreads();
        if (kc + 3 < NC) stage(kc + 3);

        const uint32_t aB = sb + (kc & (NSTG - 1)) * STG_BYTES;
        const uint32_t bB = aB + A_BYTES;

        #pragma unroll
        for (int ks = 0; ks < 2; ks++) {
            const int k0b = ks * 32;
            uint32_t a[4][4], b[2][4];
            #pragma unroll
            for (int mt = 0; mt < 4; mt++)
                ldsm4(a[mt], aB + (warpM * 64 + mt * 16 + lr) * STRB + k0b + aKoff);
            #pragma unroll
            for (int np = 0; np < 2; np++)
                ldsm4(b[np], bB + (warpN * 32 + np * 16 + bRow) * STRB + k0b + bKoff);
            #pragma unroll
            for (int nt = 0; nt < 4; nt++) {
                uint32_t b0 = b[nt >> 1][(nt & 1) * 2];
                uint32_t b1 = b[nt >> 1][(nt & 1) * 2 + 1];
                #pragma unroll
                for (int mt = 0; mt < 4; mt++)
                    mma_f16(acc[mt][nt], a[mt][0], a[mt][1], a[mt][2], a[mt][3],
                            b0, b1);
            }
        }
    }

    // ---- epilogue
    #pragma unroll
    for (int mt = 0; mt < 4; mt++) {
        size_t row = rowBase + warpM * 64 + mt * 16 + (lane >> 2);
        #pragma unroll
        for (int nt = 0; nt < 4; nt++) {
            int col = colBase + warpN * 32 + nt * 8 + 2 * (lane & 3);
            if constexpr (sizeof(TC) == 2) {
                __half* cp = (__half*)C;
                *(uint32_t*)(cp + row * N + col) =
                    pack2h(acc[mt][nt][0], acc[mt][nt][1]);
                *(uint32_t*)(cp + (row + 8) * N + col) =
                    pack2h(acc[mt][nt][2], acc[mt][nt][3]);
            } else {
                float b0 = 0.f, b1 = 0.f;
                if (bias) { b0 = bias[col]; b1 = bias[col + 1]; }
                float* cp = (float*)C;
                *(float2*)(cp + row * N + col) =
                    make_float2(acc[mt][nt][0] + b0, acc[mt][nt][1] + b1);
                *(float2*)(cp + (row + 8) * N + col) =
                    make_float2(acc[mt][nt][2] + b0, acc[mt][nt][3] + b1);
            }
        }
    }
}

// ------------------------- aux kernels --------------------------------------

__global__ void f2h_kernel(const float* __restrict__ in, __half* __restrict__ out,
                           int n4)
{
    int i = blockIdx.x * blockDim.x + threadIdx.x;
    if (i < n4) {
        float4 v = ((const float4*)in)[i];
        ((uint2*)out)[i] = make_uint2(pack2h(v.x, v.y), pack2h(v.z, v.w));
    }
}

__global__ void transpose_h(const float* __restrict__ in, __half* __restrict__ out,
                            int R, int C)
{
    __shared__ float tile[32][33];
    int c0 = blockIdx.x * 32, r0 = blockIdx.y * 32;
    #pragma unroll
    for (int i = threadIdx.y; i < 32; i += 8)
        tile[i][threadIdx.x] = in[(size_t)(r0 + i) * C + c0 + threadIdx.x];
    __syncthreads();
    #pragma unroll
    for (int i = threadIdx.y; i < 32; i += 8)
        out[(size_t)(c0 + i) * R + r0 + threadIdx.x] =
            __float2half_rn(tile[threadIdx.x][i]);
}

// ------------------------- K2: attention core (unchanged) -------------------

#define QS 72

__global__ __launch_bounds__(128)
void attn_core(const __half* __restrict__ qkv, __half* __restrict__ o)
{
    __shared__ __half Qs[32 * QS];
    __shared__ __half Ks[32 * QS];
    __shared__ __half Vs[32 * QS];
    __shared__ float  S [32][36];

    const int t    = threadIdx.x;
    const int lane = t & 31;
    const int warp = t >> 5;
    const int g    = blockIdx.x;
    const int h    = g & 7;
    const size_t tokBase = (size_t)(g >> 3) * 32;

    const __half* base = qkv + tokBase * NQKV + h * DH;

    #pragma unroll
    for (int i = 0; i < 4; i++) {
        int idx = i * 128 + t;
        int r   = idx >> 4;
        int sg  = idx & 15;
        const __half* rp = base + (size_t)r * NQKV + sg * 4;
        *(uint2*)(Qs + r * QS + sg * 4) = *(const uint2*)(rp);
        *(uint2*)(Ks + r * QS + sg * 4) = *(const uint2*)(rp + 512);
        *(uint2*)(Vs + r * QS + sg * 4) = *(const uint2*)(rp + 1024);
    }
    __syncthreads();

    const uint32_t qb = smem_u32(Qs);
    const uint32_t kb = smem_u32(Ks);
    const uint32_t vb = smem_u32(Vs);
    const int lr    = lane & 15;
    const int aKoff = (lane & 16) ? 16 : 0;
    const int bRow  = (lane & 7) + ((lane & 16) ? 8 : 0);
    const int bKoff = (lane & 8) ? 16 : 0;
    const int vCoff = (lane & 16) ? 16 : 0;

    // ---- S = Q K^T
    const int mt  = warp & 1;
    const int ntb = (warp >> 1) * 2;
    float sacc[2][4] = {{0.f,0.f,0.f,0.f},{0.f,0.f,0.f,0.f}};
    #pragma unroll
    for (int ks = 0; ks < 4; ks++) {
        const int k0b = ks * 32;
        uint32_t a[4], b[4];
        ldsm4(a, qb + (mt * 16 + lr) * (QS * 2) + k0b + aKoff);
        ldsm4(b, kb + (ntb * 8 + bRow) * (QS * 2) + k0b + bKoff);
        mma_f16(sacc[0], a[0], a[1], a[2], a[3], b[0], b[1]);
        mma_f16(sacc[1], a[0], a[1], a[2], a[3], b[2], b[3]);
    }
    #pragma unroll
    for (int n = 0; n < 2; n++) {
        int row = mt * 16 + (lane >> 2);
        int col = (ntb + n) * 8 + 2 * (lane & 3);
        S[row    ][col    ] = sacc[n][0] * ATT_SCALE;
        S[row    ][col + 1] = sacc[n][1] * ATT_SCALE;
        S[row + 8][col    ] = sacc[n][2] * ATT_SCALE;
        S[row + 8][col + 1] = sacc[n][3] * ATT_SCALE;
    }
    __syncthreads();

    // ---- softmax
    #pragma unroll
    for (int rr = 0; rr < 8; rr++) {
        int row = warp * 8 + rr;
        float v = S[row][lane];
        float m = v;
        #pragma unroll
        for (int off = 16; off; off >>= 1) m = fmaxf(m, __shfl_xor_sync(~0u, m, off));
        float e = __expf(v - m);
        float s = e;
        #pragma unroll
        for (int off = 16; off; off >>= 1) s += __shfl_xor_sync(~0u, s, off);
        S[row][lane] = e / s;
    }
    __syncthreads();

    // ---- O = P V
    const int dBase = (warp >> 1) * 32;
    float oacc[4][4];
    #pragma unroll
    for (int n = 0; n < 4; n++)
        #pragma unroll
        for (int i = 0; i < 4; i++) oacc[n][i] = 0.f;

    #pragma unroll
    for (int ks = 0; ks < 2; ks++) {
        const int j0 = ks * 16;
        int r0 = mt * 16 + (lane >> 2);
        int c  = j0 + (lane & 3) * 2;
        uint32_t a0 = pack2h(S[r0    ][c    ], S[r0    ][c + 1]);
        uint32_t a1 = pack2h(S[r0 + 8][c    ], S[r0 + 8][c + 1]);
        uint32_t a2 = pack2h(S[r0    ][c + 8], S[r0    ][c + 9]);
        uint32_t a3 = pack2h(S[r0 + 8][c + 8], S[r0 + 8][c + 9]);
        #pragma unroll
        for (int hf = 0; hf < 2; hf++) {
            uint32_t b[4];
            int dA = dBase + hf * 16;
            ldsm4t(b, vb + (j0 + lr) * (QS * 2) + dA * 2 + vCoff);
            mma_f16(oacc[hf * 2    ], a0, a1, a2, a3, b[0], b[1]);
            mma_f16(oacc[hf * 2 + 1], a0, a1, a2, a3, b[2], b[3]);
        }
    }

    __half* obase = o + tokBase * INNER + h * DH;
    const int nt4 = (warp >> 1) * 4;
    #pragma unroll
    for (int n = 0; n < 4; n++) {
        int row = mt * 16 + (lane >> 2);
        int col = (nt4 + n) * 8 + 2 * (lane & 3);
        *(uint32_t*)(obase + (size_t)row * INNER + col) =
            pack2h(oacc[n][0], oacc[n][1]);
        *(uint32_t*)(obase + (size_t)(row + 8) * INNER + col) =
            pack2h(oacc[n][2], oacc[n][3]);
    }
}

// ------------------------- launch -------------------------------------------

extern "C" void kernel_launch(void* const* d_in, const int* in_sizes, int n_in,
                              void* d_out, int out_size)
{
    const float* x     = (const float*)d_in[0];
    const float* W_qkv = (const float*)d_in[1];
    const float* W_out = (const float*)d_in[2];
    const float* b_out = (const float*)d_in[3];
    float* out = (float*)d_out;

    __half *xh, *qkv, *att, *wqT, *woT;
    cudaGetSymbolAddress((void**)&xh,  g_xh);
    cudaGetSymbolAddress((void**)&qkv, g_qkv);
    cudaGetSymbolAddress((void**)&att, g_attn);
    cudaGetSymbolAddress((void**)&wqT, g_WqkvT);
    cudaGetSymbolAddress((void**)&woT, g_WoutT);

    cudaFuncSetAttribute(gemm_h<__half>,
                         cudaFuncAttributeMaxDynamicSharedMemorySize, GSM_BYTES);
    cudaFuncSetAttribute(gemm_h<float>,
                         cudaFuncAttributeMaxDynamicSharedMemorySize, GSM_BYTES);

    const int n4 = TOKENS * DIMX / 4;
    f2h_kernel<<<n4 / 256, 256>>>(x, xh, n4);

    transpose_h<<<dim3(NQKV / 32, DIMX / 32), dim3(32, 8)>>>(W_qkv, wqT, DIMX, NQKV);
    transpose_h<<<dim3(DIMX / 32, INNER / 32), dim3(32, 8)>>>(W_out, woT, INNER, DIMX);

    // K1: qkv = xh @ W_qkv  (M=131072, K=256, N=1536)  grid (12, 1024)
    gemm_h<__half><<<dim3(NQKV / 128, TOKENS / 128), 256, GSM_BYTES>>>(
        xh, wqT, qkv, DIMX, NQKV, nullptr);

    // K2: attention
    attn_core<<<GROUPS * HEADS, 128>>>(qkv, att);

    // K3: out = att @ W_out + b  (M=131072, K=512, N=256)  grid (2, 1024)
    gemm_h<float><<<dim3(DIMX / 128, TOKENS / 128), 256, GSM_BYTES>>>(
        att, woT, out, INNER, DIMX, b_out);
}

// round 11
// speedup vs baseline: 1.2865x; 1.1420x over previous
#include <cuda_runtime.h>
#include <cuda_fp16.h>
#include <cstdint>

// ---------------------------------------------------------------------------
// Attention_37074157699274 — round 10:
//  * GEMM: K-chunk 64, 3-stage cp.async ring (half the barriers), 2 CTAs/SM.
//  * attn: one block per 32-token group, warp = head, in-register softmax
//    (QK^T C-frags == PV A-frags), single __syncthreads.
//   K0: x->fp16 ; T1/T2: weights -> [N,K] fp16
//   K1: qkv = xh @ W_qkv ; K2: attn ; K3: out = attn @ W_out + b
// ---------------------------------------------------------------------------

#define TOKENS   131072
#define GROUPS   4096
#define DIMX     256
#define NQKV     1536
#define INNER    512
#define HEADS    8
#define DH       64
#define ATT_SCALE 0.125f

__device__ __half g_xh  [(size_t)TOKENS * DIMX];
__device__ __half g_qkv [(size_t)TOKENS * NQKV];
__device__ __half g_attn[(size_t)TOKENS * INNER];
__device__ __half g_WqkvT[(size_t)NQKV * DIMX];
__device__ __half g_WoutT[(size_t)DIMX * INNER];

// ------------------------- helpers ------------------------------------------

__device__ __forceinline__ uint32_t pack2h(float x, float y) {
    __half2 h = __halves2half2(__float2half_rn(x), __float2half_rn(y));
    return *reinterpret_cast<uint32_t*>(&h);
}
__device__ __forceinline__ uint32_t smem_u32(const void* p) {
    uint32_t a;
    asm("{ .reg .u64 t; cvta.to.shared.u64 t, %1; cvt.u32.u64 %0, t; }"
        : "=r"(a) : "l"(p));
    return a;
}
__device__ __forceinline__ void cp16(uint32_t saddr, const void* gptr) {
    asm volatile("cp.async.cg.shared.global [%0], [%1], 16;"
                 :: "r"(saddr), "l"(gptr) : "memory");
}
__device__ __forceinline__ void ldsm4(uint32_t r[4], uint32_t addr) {
    asm volatile("ldmatrix.sync.aligned.m8n8.x4.shared.b16 {%0,%1,%2,%3}, [%4];"
                 : "=r"(r[0]), "=r"(r[1]), "=r"(r[2]), "=r"(r[3]) : "r"(addr));
}
__device__ __forceinline__ void ldsm4t(uint32_t r[4], uint32_t addr) {
    asm volatile("ldmatrix.sync.aligned.m8n8.x4.trans.shared.b16 {%0,%1,%2,%3}, [%4];"
                 : "=r"(r[0]), "=r"(r[1]), "=r"(r[2]), "=r"(r[3]) : "r"(addr));
}
__device__ __forceinline__ void mma_f16(float c[4], uint32_t a0, uint32_t a1,
                                        uint32_t a2, uint32_t a3,
                                        uint32_t b0, uint32_t b1) {
    asm volatile(
        "mma.sync.aligned.m16n8k16.row.col.f32.f16.f16.f32 "
        "{%0,%1,%2,%3}, {%4,%5,%6,%7}, {%8,%9}, {%0,%1,%2,%3};\n"
        : "+f"(c[0]), "+f"(c[1]), "+f"(c[2]), "+f"(c[3])
        : "r"(a0), "r"(a1), "r"(a2), "r"(a3), "r"(b0), "r"(b1));
}

// ------------------------- GEMM ---------------------------------------------
// C[M,N] = A[M,K] @ Bt[N,K]^T (+bias). CTA 128x128, K-chunk 64, 3-stage
// cp.async ring, 256 threads = 8 warps 2(M)x4(N), warp tile 64x32, ldmatrix.
// smem rows = 72 halfs (144 B; 144 mod 128 = 16 -> conflict-free ldsm).

#define STRB   144
#define A_BYTES (128 * STRB)              // 18432
#define B_BYTES (128 * STRB)              // 18432
#define STG_BYTES (A_BYTES + B_BYTES)     // 36864
#define NSTG   3
#define GSM_BYTES (NSTG * STG_BYTES)      // 110592

template<typename TC>
__global__ __launch_bounds__(256, 2)
void gemm_h(const __half* __restrict__ A, const __half* __restrict__ Bt,
            TC* __restrict__ C, int K, int N, const float* __restrict__ bias)
{
    extern __shared__ __half sh[];
    const uint32_t sb = smem_u32(sh);

    const int t     = threadIdx.x;
    const int lane  = t & 31;
    const int warp  = t >> 5;             // 0..7
    const int warpM = warp & 1;           // 0..1 -> rows [warpM*64, +64)
    const int warpN = warp >> 1;          // 0..3 -> cols [warpN*32, +32)

    const size_t rowBase = (size_t)blockIdx.y * 128;
    const int    colBase = blockIdx.x * 128;
    const int NC = K >> 6;                // chunks of 64

    float acc[4][4][4];
    #pragma unroll
    for (int mt = 0; mt < 4; mt++)
        #pragma unroll
        for (int nt = 0; nt < 4; nt++)
            #pragma unroll
            for (int i = 0; i < 4; i++) acc[mt][nt][i] = 0.f;

    const __half* Ab = A  + rowBase * K;
    const __half* Bb = Bt + (size_t)colBase * K;

    auto stage = [&](int kc) {
        const int slot = kc % NSTG;
        const uint32_t aD = sb + slot * STG_BYTES;
        const uint32_t bD = aD + A_BYTES;
        const __half* As = Ab + kc * 64;
        const __half* Bs = Bb + kc * 64;
        #pragma unroll
        for (int i = 0; i < 4; i++) {            // A: 1024 16B-granules
            int g = i * 256 + t, r = g >> 3, s = g & 7;
            cp16(aD + r * STRB + s * 16, As + (size_t)r * K + s * 8);
        }
        #pragma unroll
        for (int i = 0; i < 4; i++) {            // B: 1024 granules
            int g = i * 256 + t, r = g >> 3, s = g & 7;
            cp16(bD + r * STRB + s * 16, Bs + (size_t)r * K + s * 8);
        }
        asm volatile("cp.async.commit_group;" ::: "memory");
    };

    stage(0); stage(1);

    const int lr    = lane & 15;
    const int aKoff = (lane & 16) ? 16 : 0;
    const int bRow  = (lane & 7) + ((lane & 16) ? 8 : 0);
    const int bKoff = (lane & 8) ? 16 : 0;

    for (int kc = 0; kc < NC; kc++) {
        if (kc < NC - 1) asm volatile("cp.async.wait_group 1;" ::: "memory");
        else             asm volatile("cp.async.wait_group 0;" ::: "memory");
        __syncthreads();
        if (kc + 2 < NC) stage(kc + 2);

        const uint32_t aB = sb + (kc % NSTG) * STG_BYTES;
        const uint32_t bB = aB + A_BYTES;

        #pragma unroll
        for (int ks = 0; ks < 4; ks++) {
            const int k0b = ks * 32;
            uint32_t a[4][4], b[2][4];
            #pragma unroll
            for (int mt = 0; mt < 4; mt++)
                ldsm4(a[mt], aB + (warpM * 64 + mt * 16 + lr) * STRB + k0b + aKoff);
            #pragma unroll
            for (int np = 0; np < 2; np++)
                ldsm4(b[np], bB + (warpN * 32 + np * 16 + bRow) * STRB + k0b + bKoff);
            #pragma unroll
            for (int nt = 0; nt < 4; nt++) {
                uint32_t b0 = b[nt >> 1][(nt & 1) * 2];
                uint32_t b1 = b[nt >> 1][(nt & 1) * 2 + 1];
                #pragma unroll
                for (int mt = 0; mt < 4; mt++)
                    mma_f16(acc[mt][nt], a[mt][0], a[mt][1], a[mt][2], a[mt][3],
                            b0, b1);
            }
        }
    }

    // ---- epilogue
    #pragma unroll
    for (int mt = 0; mt < 4; mt++) {
        size_t row = rowBase + warpM * 64 + mt * 16 + (lane >> 2);
        #pragma unroll
        for (int nt = 0; nt < 4; nt++) {
            int col = colBase + warpN * 32 + nt * 8 + 2 * (lane & 3);
            if constexpr (sizeof(TC) == 2) {
                __half* cp = (__half*)C;
                *(uint32_t*)(cp + row * N + col) =
                    pack2h(acc[mt][nt][0], acc[mt][nt][1]);
                *(uint32_t*)(cp + (row + 8) * N + col) =
                    pack2h(acc[mt][nt][2], acc[mt][nt][3]);
            } else {
                float b0 = 0.f, b1 = 0.f;
                if (bias) { b0 = bias[col]; b1 = bias[col + 1]; }
                float* cp = (float*)C;
                *(float2*)(cp + row * N + col) =
                    make_float2(acc[mt][nt][0] + b0, acc[mt][nt][1] + b1);
                *(float2*)(cp + (row + 8) * N + col) =
                    make_float2(acc[mt][nt][2] + b0, acc[mt][nt][3] + b1);
            }
        }
    }
}

// ------------------------- aux kernels --------------------------------------

__global__ void f2h_kernel(const float* __restrict__ in, __half* __restrict__ out,
                           int n4)
{
    int i = blockIdx.x * blockDim.x + threadIdx.x;
    if (i < n4) {
        float4 v = ((const float4*)in)[i];
        ((uint2*)out)[i] = make_uint2(pack2h(v.x, v.y), pack2h(v.z, v.w));
    }
}

__global__ void transpose_h(const float* __restrict__ in, __half* __restrict__ out,
                            int R, int C)
{
    __shared__ float tile[32][33];
    int c0 = blockIdx.x * 32, r0 = blockIdx.y * 32;
    #pragma unroll
    for (int i = threadIdx.y; i < 32; i += 8)
        tile[i][threadIdx.x] = in[(size_t)(r0 + i) * C + c0 + threadIdx.x];
    __syncthreads();
    #pragma unroll
    for (int i = threadIdx.y; i < 32; i += 8)
        out[(size_t)(c0 + i) * R + r0 + threadIdx.x] =
            __float2half_rn(tile[threadIdx.x][i]);
}

// ------------------------- K2: attention, warp = head -----------------------
// One block per 32-token group. 256 threads = 8 warps; warp w handles head w.
// QKV rows (32 x 1536) staged once, padded to 1544 halfs (3088 B, 16 mod 128
// -> ldsm conflict-free). S lives in registers; softmax via quad shuffles.

#define ROWH 1544
#define ROWB (ROWH * 2)                   // 3088 bytes
#define ASM_BYTES (32 * ROWB)             // 98816

__global__ __launch_bounds__(256)
void attn_core(const __half* __restrict__ qkv, __half* __restrict__ o)
{
    extern __shared__ __half T[];
    const uint32_t tb = smem_u32(T);

    const int t    = threadIdx.x;
    const int lane = t & 31;
    const int h    = t >> 5;              // warp = head
    const size_t tokBase = (size_t)blockIdx.x * 32;

    // stage 32 rows x 1536 halfs (uint4 = 8 halfs; 192 per row)
    {
        const __half* src = qkv + tokBase * NQKV;
        #pragma unroll
        for (int i = 0; i < 24; i++) {
            int idx = i * 256 + t;        // 0..6143
            int r = idx / 192, c = idx % 192;
            *(uint4*)(T + r * ROWH + c * 8) = *(const uint4*)(src + (size_t)r * NQKV + c * 8);
        }
    }
    __syncthreads();

    const uint32_t qOff = tb + h * 128;             // q slice of each row
    const uint32_t kOff = tb + 1024 + h * 128;      // k slice
    const uint32_t vOff = tb + 2048 + h * 128;      // v slice

    const int lr    = lane & 15;
    const int aKoff = (lane & 16) ? 16 : 0;
    const int bRow  = (lane & 7) + ((lane & 16) ? 8 : 0);
    const int bKoff = (lane & 8) ? 16 : 0;
    const int vCoff = (lane & 16) ? 16 : 0;

    // ---- S = Q K^T : 32x32, K=64. s[mt][nt][4]
    float s[2][4][4];
    #pragma unroll
    for (int mt = 0; mt < 2; mt++)
        #pragma unroll
        for (int nt = 0; nt < 4; nt++)
            #pragma unroll
            for (int i = 0; i < 4; i++) s[mt][nt][i] = 0.f;

    #pragma unroll
    for (int kt = 0; kt < 4; kt++) {
        const int k0b = kt * 32;
        uint32_t a[2][4], b[2][4];
        #pragma unroll
        for (int mt = 0; mt < 2; mt++)
            ldsm4(a[mt], qOff + (mt * 16 + lr) * ROWB + k0b + aKoff);
        #pragma unroll
        for (int nb = 0; nb < 2; nb++)
            ldsm4(b[nb], kOff + (nb * 16 + bRow) * ROWB + k0b + bKoff);
        #pragma unroll
        for (int mt = 0; mt < 2; mt++)
            #pragma unroll
            for (int nb = 0; nb < 2; nb++) {
                mma_f16(s[mt][2 * nb    ], a[mt][0], a[mt][1], a[mt][2], a[mt][3],
                        b[nb][0], b[nb][1]);
                mma_f16(s[mt][2 * nb + 1], a[mt][0], a[mt][1], a[mt][2], a[mt][3],
                        b[nb][2], b[nb][3]);
            }
    }

    // scale
    #pragma unroll
    for (int mt = 0; mt < 2; mt++)
        #pragma unroll
        for (int nt = 0; nt < 4; nt++)
            #pragma unroll
            for (int i = 0; i < 4; i++) s[mt][nt][i] *= ATT_SCALE;

    // ---- softmax in registers. Row A = {c0,c1} idx, row B = {c2,c3}.
    // Each row is spread over the lane quad (l&3) with 8 values per lane.
    #pragma unroll
    for (int mt = 0; mt < 2; mt++) {
        float mA = -1e30f, mB = -1e30f;
        #pragma unroll
        for (int nt = 0; nt < 4; nt++) {
            mA = fmaxf(mA, fmaxf(s[mt][nt][0], s[mt][nt][1]));
            mB = fmaxf(mB, fmaxf(s[mt][nt][2], s[mt][nt][3]));
        }
        mA = fmaxf(mA, __shfl_xor_sync(~0u, mA, 1));
        mA = fmaxf(mA, __shfl_xor_sync(~0u, mA, 2));
        mB = fmaxf(mB, __shfl_xor_sync(~0u, mB, 1));
        mB = fmaxf(mB, __shfl_xor_sync(~0u, mB, 2));
        float sA = 0.f, sB = 0.f;
        #pragma unroll
        for (int nt = 0; nt < 4; nt++) {
            s[mt][nt][0] = __expf(s[mt][nt][0] - mA); sA += s[mt][nt][0];
            s[mt][nt][1] = __expf(s[mt][nt][1] - mA); sA += s[mt][nt][1];
            s[mt][nt][2] = __expf(s[mt][nt][2] - mB); sB += s[mt][nt][2];
            s[mt][nt][3] = __expf(s[mt][nt][3] - mB); sB += s[mt][nt][3];
        }
        sA += __shfl_xor_sync(~0u, sA, 1);
        sA += __shfl_xor_sync(~0u, sA, 2);
        sB += __shfl_xor_sync(~0u, sB, 1);
        sB += __shfl_xor_sync(~0u, sB, 2);
        float iA = 1.f / sA, iB = 1.f / sB;
        #pragma unroll
        for (int nt = 0; nt < 4; nt++) {
            s[mt][nt][0] *= iA; s[mt][nt][1] *= iA;
            s[mt][nt][2] *= iB; s[mt][nt][3] *= iB;
        }
    }

    // ---- pack P into A-fragments: C-frag layout == A-frag layout.
    // kt selects j-cols [kt*16, +16) = ntiles {2kt, 2kt+1}.
    uint32_t pk[2][2][4];
    #pragma unroll
    for (int mt = 0; mt < 2; mt++)
        #pragma unroll
        for (int kt = 0; kt < 2; kt++) {
            pk[mt][kt][0] = pack2h(s[mt][2 * kt    ][0], s[mt][2 * kt    ][1]);
            pk[mt][kt][1] = pack2h(s[mt][2 * kt    ][2], s[mt][2 * kt    ][3]);
            pk[mt][kt][2] = pack2h(s[mt][2 * kt + 1][0], s[mt][2 * kt + 1][1]);
            pk[mt][kt][3] = pack2h(s[mt][2 * kt + 1][2], s[mt][2 * kt + 1][3]);
        }

    // ---- O = P V : 32x64, K=32. V B-frags via ldmatrix.trans.
    float oa[2][8][4];
    #pragma unroll
    for (int mt = 0; mt < 2; mt++)
        #pragma unroll
        for (int nt = 0; nt < 8; nt++)
            #pragma unroll
            for (int i = 0; i < 4; i++) oa[mt][nt][i] = 0.f;

    #pragma unroll
    for (int kt = 0; kt < 2; kt++) {
        #pragma unroll
        for (int hf = 0; hf < 4; hf++) {
            uint32_t b[4];
            ldsm4t(b, vOff + (kt * 16 + lr) * ROWB + hf * 32 + vCoff);
            #pragma unroll
            for (int mt = 0; mt < 2; mt++) {
                mma_f16(oa[mt][2 * hf    ], pk[mt][kt][0], pk[mt][kt][1],
                        pk[mt][kt][2], pk[mt][kt][3], b[0], b[1]);
                mma_f16(oa[mt][2 * hf + 1], pk[mt][kt][0], pk[mt][kt][1],
                        pk[mt][kt][2], pk[mt][kt][3], b[2], b[3]);
            }
        }
    }

    // ---- epilogue -> g_attn[tok, h*64 + d]
    __half* obase = o + tokBase * INNER + h * DH;
    #pragma unroll
    for (int mt = 0; mt < 2; mt++) {
        int row = mt * 16 + (lane >> 2);
        #pragma unroll
        for (int nt = 0; nt < 8; nt++) {
            int col = nt * 8 + 2 * (lane & 3);
            *(uint32_t*)(obase + (size_t)row * INNER + col) =
                pack2h(oa[mt][nt][0], oa[mt][nt][1]);
            *(uint32_t*)(obase + (size_t)(row + 8) * INNER + col) =
                pack2h(oa[mt][nt][2], oa[mt][nt][3]);
        }
    }
}

// ------------------------- launch -------------------------------------------

extern "C" void kernel_launch(void* const* d_in, const int* in_sizes, int n_in,
                              void* d_out, int out_size)
{
    const float* x     = (const float*)d_in[0];
    const float* W_qkv = (const float*)d_in[1];
    const float* W_out = (const float*)d_in[2];
    const float* b_out = (const float*)d_in[3];
    float* out = (float*)d_out;

    __half *xh, *qkv, *att, *wqT, *woT;
    cudaGetSymbolAddress((void**)&xh,  g_xh);
    cudaGetSymbolAddress((void**)&qkv, g_qkv);
    cudaGetSymbolAddress((void**)&att, g_attn);
    cudaGetSymbolAddress((void**)&wqT, g_WqkvT);
    cudaGetSymbolAddress((void**)&woT, g_WoutT);

    cudaFuncSetAttribute(gemm_h<__half>,
                         cudaFuncAttributeMaxDynamicSharedMemorySize, GSM_BYTES);
    cudaFuncSetAttribute(gemm_h<float>,
                         cudaFuncAttributeMaxDynamicSharedMemorySize, GSM_BYTES);
    cudaFuncSetAttribute(attn_core,
                         cudaFuncAttributeMaxDynamicSharedMemorySize, ASM_BYTES);

    const int n4 = TOKENS * DIMX / 4;
    f2h_kernel<<<n4 / 256, 256>>>(x, xh, n4);

    transpose_h<<<dim3(NQKV / 32, DIMX / 32), dim3(32, 8)>>>(W_qkv, wqT, DIMX, NQKV);
    transpose_h<<<dim3(DIMX / 32, INNER / 32), dim3(32, 8)>>>(W_out, woT, INNER, DIMX);

    // K1: qkv = xh @ W_qkv  (M=131072, K=256, N=1536)
    gemm_h<__half><<<dim3(NQKV / 128, TOKENS / 128), 256, GSM_BYTES>>>(
        xh, wqT, qkv, DIMX, NQKV, nullptr);

    // K2: attention (one block per group)
    attn_core<<<GROUPS, 256, ASM_BYTES>>>(qkv, att);

    // K3: out = att @ W_out + b  (M=131072, K=512, N=256)
    gemm_h<float><<<dim3(DIMX / 128, TOKENS / 128), 256, GSM_BYTES>>>(
        att, woT, out, INNER, DIMX, b_out);
}